// round 8
// baseline (speedup 1.0000x reference)
#include <cuda_runtime.h>
#include <math.h>

#define NT 256
#define TILE 16
#define SEQ 5
#define ROWS (TILE*SEQ)
#define EMAX 150016
#define NMAX 50048

typedef unsigned long long ull;

static __device__ float    g_eft[(size_t)EMAX * 512];
static __device__ float    g_a[EMAX * 8];
static __device__ float    g_aexp[EMAX * 8];
static __device__ unsigned g_mx[NMAX * 8];
static __device__ float    g_sm[NMAX * 8];

// smem layout (floats)
#define O_TOK  0
#define O_X    (O_TOK + ROWS*64)
#define O_BUF  (O_X + ROWS*64)            // [80][192] / [16][256]
#define O_W    (O_BUF + ROWS*192)         // 16384 floats: transposed weight stage
#define O_INST (O_W + 16384)
#define O_Q    (O_INST + TILE*64)
#define O_FV   (O_Q + TILE*64)
#define O_DEN  (O_FV + ROWS)
#define O_INT  (O_DEN + TILE)
#define SMEM_FLOATS (O_INT + 112)
#define SMEM_BYTES (SMEM_FLOATS*4)

__device__ __forceinline__ void fma2(ull& c, ull a, ull b){
    asm("fma.rn.f32x2 %0, %1, %2, %0;" : "+l"(c) : "l"(a), "l"(b));
}
__device__ __forceinline__ float hsum2(ull c){
    float lo, hi;
    asm("mov.b64 {%0,%1}, %2;" : "=f"(lo), "=f"(hi) : "l"(c));
    return lo + hi;
}
__device__ __forceinline__ void unpack2(ull c, float& lo, float& hi){
    asm("mov.b64 {%0,%1}, %2;" : "=f"(lo), "=f"(hi) : "l"(c));
}
__device__ __forceinline__ ull bcast2(float s){
    ull r; asm("mov.b64 %0, {%1,%1};" : "=l"(r) : "f"(s)); return r;
}
__device__ __forceinline__ ull pack2(float lo, float hi){
    ull r; asm("mov.b64 %0, {%1,%2};" : "=l"(r) : "f"(lo), "f"(hi)); return r;
}
__device__ __forceinline__ float warpSum(float v){
#pragma unroll
    for (int o=16;o>0;o>>=1) v += __shfl_xor_sync(0xffffffffu, v, o);
    return v;
}
__device__ __forceinline__ float geluf(float x){
    return 0.5f*x*(1.0f+erff(x*0.70710678118654752f));
}
__device__ __forceinline__ unsigned fkey(float f){
    unsigned u = __float_as_uint(f);
    return (u & 0x80000000u) ? ~u : (u | 0x80000000u);
}
__device__ __forceinline__ float kdec(unsigned k){
    return (k & 0x80000000u) ? __uint_as_float(k & 0x7fffffffu) : __uint_as_float(~k);
}

// Stage W[NC][K] (row-major global) into transposed packed smem:
// Wt[k4][col] = ulonglong2{ (W[col][4k4],W[col][4k4+1]), (W[col][4k4+2],W[col][4k4+3]) }.
// Writes are stride-1 across lanes (conflict-free); GEMM reads of Wt[k4*NC+col]
// are lane-consecutive LDS.128 (conflict-free).
__device__ void stageT(ulonglong2* dst,const float* src,int NCc,int K,int tid){
    int K4 = K >> 2;
    for (int i = tid; i < NCc*K4; i += NT){
        int col = i % NCc, k4 = i / NCc;
        float4 v = __ldg((const float4*)(src + col*K + k4*4));
        ulonglong2 t; t.x = pack2(v.x, v.y); t.y = pack2(v.z, v.w);
        dst[k4*NCc + col] = t;
    }
}

// M=80 GEMM: out[80][ldo] op= X[80][ldx] @ W^T + bias.  K=64.
// Wt = transposed stage (ldc = staged column count, may exceed NC for sub-views).
// Task = 2 cols x 10 rows; tasks = (NC/2)*8 (multiples of NT for NC=64/128/192).
__device__ void gemm80(float* out,int ldo,const float* X,int ldx,
                       const ulonglong2* Wt,int ldc,const float* bias,
                       int NC,bool acc,int tid){
    int ncc = NC >> 1;
    int total = ncc * 8;
    for (int t = tid; t < total; t += NT){
        int col = t % ncc;
        int r0  = (t / ncc) * 10;
        const ulonglong2* W0 = Wt + col;
        const ulonglong2* W1 = Wt + col + ncc;
        ull a0[10], a1[10];
#pragma unroll
        for (int i=0;i<10;i++){ a0[i]=0ull; a1[i]=0ull; }
#pragma unroll 4
        for (int k4=0;k4<16;k4++){
            ulonglong2 w0 = W0[k4*ldc];
            ulonglong2 w1 = W1[k4*ldc];
#pragma unroll
            for (int i=0;i<10;i++){
                ulonglong2 xv = *(const ulonglong2*)(X + (r0+i)*ldx + k4*4);
                fma2(a0[i], xv.x, w0.x); fma2(a0[i], xv.y, w0.y);
                fma2(a1[i], xv.x, w1.x); fma2(a1[i], xv.y, w1.y);
            }
        }
        float b0 = __ldg(bias+col), b1 = __ldg(bias+col+ncc);
#pragma unroll
        for (int i=0;i<10;i++){
            float v0 = hsum2(a0[i]) + b0;
            float v1 = hsum2(a1[i]) + b1;
            float* p0 = out + (r0+i)*ldo + col;
            float* p1 = out + (r0+i)*ldo + col + ncc;
            if (acc){ *p0 += v0; *p1 += v1; }
            else    { *p0  = v0; *p1  = v1; }
        }
    }
}

// M=16 GEMM, split-K when NC<NT. s_part needs (NT/NC)*16*NC = 4096 floats max.
__device__ void gemm16(float* out,int ldo,const float* X,int ldx,
                       const ulonglong2* Wt,int ldc,const float* bias,
                       int NC,int K,bool acc,int tid,float* s_part){
    int KS = NT / NC; if (KS < 1) KS = 1;
    if (KS == 1){
        if (tid < NC){
            int col = tid;
            int K4 = K >> 2;
            ull a[16];
#pragma unroll
            for (int i=0;i<16;i++) a[i]=0ull;
            for (int k4=0;k4<K4;k4++){
                ulonglong2 wv = Wt[k4*ldc + col];
#pragma unroll
                for (int i=0;i<16;i++){
                    ulonglong2 xv = *(const ulonglong2*)(X + i*ldx + k4*4);
                    fma2(a[i], xv.x, wv.x); fma2(a[i], xv.y, wv.y);
                }
            }
            float bv = bias ? __ldg(bias+col) : 0.f;
#pragma unroll
            for (int i=0;i<16;i++){
                float v = hsum2(a[i]) + bv;
                float* p = out + i*ldo + col;
                if (acc) *p += v; else *p = v;
            }
        }
        return;
    }
    {
        int col = tid % NC, ks = tid / NC;
        int kl = K / KS, kl4 = kl >> 2;
        const ulonglong2* Wc = Wt + ks*kl4*ldc + col;
        const float* Xc = X + ks*kl;
        ull a[16];
#pragma unroll
        for (int i=0;i<16;i++) a[i]=0ull;
        for (int k4=0;k4<kl4;k4++){
            ulonglong2 wv = Wc[k4*ldc];
#pragma unroll
            for (int i=0;i<16;i++){
                ulonglong2 xv = *(const ulonglong2*)(Xc + i*ldx + k4*4);
                fma2(a[i], xv.x, wv.x); fma2(a[i], xv.y, wv.y);
            }
        }
        float* pp = s_part + ks*NC*16 + col;
#pragma unroll
        for (int i=0;i<16;i++) pp[i*NC] = hsum2(a[i]);
    }
    __syncthreads();
    int KSc = NT / NC;
    for (int i = tid; i < 16*NC; i += NT){
        int col = i % NC;
        float s = 0.f;
        for (int ks=0; ks<KSc; ks++) s += s_part[ks*NC*16 + i];
        float v = s + (bias ? __ldg(bias+col) : 0.f);
        float* p = out + (i/NC)*ldo + col;
        if (acc) *p += v; else *p = v;
    }
}

__device__ void ln_rows(const float* in,float* out,int nrows,
                        const float* g,const float* b,int tid){
    int warp = tid >> 5, lane = tid & 31;
    for (int r = warp; r < nrows; r += 8){
        float x0 = in[r*64+lane], x1 = in[r*64+lane+32];
        float s  = warpSum(x0+x1);
        float s2 = warpSum(x0*x0 + x1*x1);
        float m  = s*(1.f/64.f);
        float v  = fmaxf(s2*(1.f/64.f) - m*m, 0.f);
        float rs = rsqrtf(v + 1e-5f);
        out[r*64+lane]    = (x0-m)*rs*__ldg(g+lane)    + __ldg(b+lane);
        out[r*64+lane+32] = (x1-m)*rs*__ldg(g+lane+32) + __ldg(b+lane+32);
    }
}

__global__ void __launch_bounds__(NT,1)
k_mega(const float* __restrict__ feat,const float* __restrict__ pos,
       const float* __restrict__ siw,const float* __restrict__ sib,
       const float* __restrict__ sow,const float* __restrict__ sob,
       const float* __restrict__ ciw,const float* __restrict__ cib,
       const float* __restrict__ cow,const float* __restrict__ cob,
       const float* __restrict__ sl1g,const float* __restrict__ sl1b,
       const float* __restrict__ sl2g,const float* __restrict__ sl2b,
       const float* __restrict__ cl1g,const float* __restrict__ cl1b,
       const float* __restrict__ cl2g,const float* __restrict__ cl2b,
       const float* __restrict__ fw1,const float* __restrict__ fb1,
       const float* __restrict__ fw2,const float* __restrict__ fb2,
       const float* __restrict__ gw1,const float* __restrict__ gb1,
       const float* __restrict__ gw2,const float* __restrict__ gb2,
       const float* __restrict__ iw,const float* __restrict__ av,
       const int* __restrict__ eidx,const int* __restrict__ dst,int N,int E)
{
    extern __shared__ float sm[];
    float* s_tok = sm + O_TOK;  float* s_x = sm + O_X;
    float* s_buf = sm + O_BUF;
    ulonglong2* s_w = (ulonglong2*)(sm + O_W);
    float* s_inst= sm + O_INST; float* s_q = sm + O_Q;
    float* s_fv  = sm + O_FV;   float* s_den = sm + O_DEN;
    int* s_idx = (int*)(sm + O_INT);
    int* s_dst = s_idx + ROWS;  int* s_lid = s_dst + TILE;
    int tid = threadIdx.x, e0 = blockIdx.x * TILE;

    // S0: indices, validity, stats, gather tokens(+pos)
    if (tid < ROWS){
        int e = tid/SEQ, s = tid - e*SEQ, ge = e0 + e;
        int id = (ge < E) ? eidx[ge*SEQ + s] : N;
        s_idx[tid] = id; s_fv[tid] = (id < N) ? 1.f : 0.f;
    }
    __syncthreads();
    if (tid < TILE){
        float c = 0.f;
        for (int s=0;s<SEQ;s++) c += s_fv[tid*SEQ+s];
        s_den[tid] = fmaxf(c, 1.f);
        int lp = (c > 0.f) ? (int)c - 1 : 0;
        s_lid[tid] = s_idx[tid*SEQ + lp];
        int ge = e0 + tid;
        s_dst[tid] = (ge < E) ? dst[ge] : 0;
    }
    for (int i = tid; i < ROWS*64; i += NT){
        int r = i>>6, c = i&63, s = r%SEQ, id = s_idx[r];
        s_tok[i] = (id < N) ? __ldg(feat + (size_t)id*64 + c) + __ldg(pos + s*64 + c) : 0.f;
    }
    __syncthreads();

    // S1: LN1 + QKV (M=80, NC=192)
    ln_rows(s_tok, s_x, ROWS, sl1g, sl1b, tid);
    stageT(s_w, siw, 192, 64, tid);
    __syncthreads();
    gemm80(s_buf, 192, s_x, 64, s_w, 192, sib, 192, false, tid);
    __syncthreads();

    // S2: self attention, 640 items = (edge, head, q-pos), all 256 threads
    for (int it = tid; it < TILE*8*SEQ; it += NT){
        int qs = it % SEQ; int eh = it / SEQ; int h = eh & 7; int e = eh >> 3;
        const float* bb = s_buf + e*SEQ*192;
        const ull* q8 = (const ull*)(bb + qs*192 + h*8);
        ull q0=q8[0], q1=q8[1], q2=q8[2], q3=q8[3];
        float sc[SEQ], mx = -1e30f;
#pragma unroll
        for (int ks=0; ks<SEQ; ks++){
            const ull* kk = (const ull*)(bb + ks*192 + 64 + h*8);
            ull acc = 0ull;
            fma2(acc, q0, kk[0]); fma2(acc, q1, kk[1]);
            fma2(acc, q2, kk[2]); fma2(acc, q3, kk[3]);
            float s = hsum2(acc) * 0.35355339059327373f;
            if (s_fv[e*SEQ+ks] == 0.f) s = -1e9f;
            sc[ks] = s; mx = fmaxf(mx, s);
        }
        float sum = 0.f;
#pragma unroll
        for (int ks=0; ks<SEQ; ks++){ sc[ks] = expf(sc[ks]-mx); sum += sc[ks]; }
        float inv = 1.f/sum;
        ull o[4] = {0ull,0ull,0ull,0ull};
#pragma unroll
        for (int ks=0; ks<SEQ; ks++){
            ull w2 = bcast2(sc[ks]);
            const ull* vv = (const ull*)(bb + ks*192 + 128 + h*8);
            fma2(o[0], w2, vv[0]); fma2(o[1], w2, vv[1]);
            fma2(o[2], w2, vv[2]); fma2(o[3], w2, vv[3]);
        }
        float* op = s_x + (e*SEQ+qs)*64 + h*8;
#pragma unroll
        for (int j=0;j<4;j++){
            float lo, hi; unpack2(o[j], lo, hi);
            op[2*j] = lo*inv; op[2*j+1] = hi*inv;
        }
    }
    stageT(s_w, sow, 64, 64, tid);
    __syncthreads();
    gemm80(s_tok, 64, s_x, 64, s_w, 64, sob, 64, true, tid);
    __syncthreads();

    // S3: masked mean pool
    for (int i = tid; i < TILE*64; i += NT){
        int e = i>>6, c = i&63; float s = 0.f;
#pragma unroll
        for (int ss=0; ss<SEQ; ss++) s += s_fv[e*SEQ+ss]*s_tok[(e*SEQ+ss)*64+c];
        s_inst[i] = s / s_den[e];
    }
    __syncthreads();

    // S4: FF (sa)
    ln_rows(s_inst, s_x, TILE, sl2g, sl2b, tid);
    stageT(s_w, fw1, 256, 64, tid);
    __syncthreads();
    gemm16(s_buf, 256, s_x, 64, s_w, 256, fb1, 256, 64, false, tid, s_x+1024);
    __syncthreads();
    for (int i = tid; i < TILE*256; i += NT) s_buf[i] = geluf(s_buf[i]);
    stageT(s_w, fw2, 64, 256, tid);
    __syncthreads();
    gemm16(s_inst, 64, s_buf, 256, s_w, 64, fb2, 64, 256, true, tid, s_x);
    __syncthreads();

    // S5: cross attention
    for (int i = tid; i < TILE*64; i += NT){
        int e = i>>6, c = i&63, id = s_lid[e];
        s_x[i] = (id < N) ? __ldg(feat + (size_t)id*64 + c) : 0.f;
    }
    __syncthreads();
    ln_rows(s_x, s_x, TILE, cl1g, cl1b, tid);
    stageT(s_w, ciw, 192, 64, tid);
    __syncthreads();
    gemm16(s_q, 64, s_x, 64, s_w, 192, cib, 64, 64, false, tid, s_x+1024);
    __syncthreads();
    gemm80(s_buf+64, 192, s_tok, 64, s_w+64, 192, cib+64, 128, false, tid);
    __syncthreads();
    if (tid < TILE*8){
        int e = tid>>3, h = tid&7;
        const ull* qq = (const ull*)(s_q + e*64 + h*8);
        ull q0=qq[0], q1=qq[1], q2=qq[2], q3=qq[3];
        float sc[SEQ], mx = -1e30f;
#pragma unroll
        for (int ks=0; ks<SEQ; ks++){
            const ull* kk = (const ull*)(s_buf + (e*SEQ+ks)*192 + 64 + h*8);
            ull acc = 0ull;
            fma2(acc, q0, kk[0]); fma2(acc, q1, kk[1]);
            fma2(acc, q2, kk[2]); fma2(acc, q3, kk[3]);
            float s = hsum2(acc) * 0.35355339059327373f;
            if (s_fv[e*SEQ+ks] == 0.f) s = -1e9f;
            sc[ks] = s; mx = fmaxf(mx, s);
        }
        float sum = 0.f;
#pragma unroll
        for (int ks=0; ks<SEQ; ks++){ sc[ks] = expf(sc[ks]-mx); sum += sc[ks]; }
        float inv = 1.f/sum;
        ull o[4] = {0ull,0ull,0ull,0ull};
#pragma unroll
        for (int ks=0; ks<SEQ; ks++){
            ull w2 = bcast2(sc[ks]);
            const ull* vv = (const ull*)(s_buf + (e*SEQ+ks)*192 + 128 + h*8);
            fma2(o[0], w2, vv[0]); fma2(o[1], w2, vv[1]);
            fma2(o[2], w2, vv[2]); fma2(o[3], w2, vv[3]);
        }
        float* op = s_x + e*64 + h*8;
#pragma unroll
        for (int j=0;j<4;j++){
            float lo, hi; unpack2(o[j], lo, hi);
            op[2*j] = lo*inv; op[2*j+1] = hi*inv;
        }
    }
    stageT(s_w, cow, 64, 64, tid);
    __syncthreads();
    gemm16(s_inst, 64, s_x, 64, s_w, 64, cob, 64, 64, true, tid, s_x+1024);
    __syncthreads();

    // S6: FF (ca)
    ln_rows(s_inst, s_x, TILE, cl2g, cl2b, tid);
    stageT(s_w, gw1, 256, 64, tid);
    __syncthreads();
    gemm16(s_buf, 256, s_x, 64, s_w, 256, gb1, 256, 64, false, tid, s_x+1024);
    __syncthreads();
    for (int i = tid; i < TILE*256; i += NT) s_buf[i] = geluf(s_buf[i]);
    stageT(s_w, gw2, 64, 256, tid);
    __syncthreads();
    gemm16(s_inst, 64, s_buf, 256, s_w, 64, gb2, 64, 256, true, tid, s_x);
    __syncthreads();

    // S7: eft = inst @ inst_w^T (2 chunks of 256 cols) + score + seg max
    for (int ch = 0; ch < 2; ch++){
        stageT(s_w, iw + ch*256*64, 256, 64, tid);
        __syncthreads();
        gemm16(s_buf, 256, s_inst, 64, s_w, 256, (const float*)0, 256, 64, false, tid, s_x);
        __syncthreads();
        for (int i = tid; i < TILE*256; i += NT){
            int r = i>>8, c = i&255, ge = e0 + r;
            if (ge < E) g_eft[(size_t)ge*512 + ch*256 + c] = s_buf[i];
        }
        if (tid < TILE*4){
            int e = tid>>2, h4 = tid&3, h = ch*4+h4, ge = e0 + e;
            float v = 0.f;
            for (int d=0; d<64; d++) v += s_buf[e*256 + h4*64 + d]*__ldg(av + h*64 + d);
            v = (v > 0.f) ? v : 0.01f*v;
            if (ge < E){
                g_a[ge*8+h] = v;
                atomicMax(&g_mx[(size_t)s_dst[e]*8 + h], fkey(v));
            }
        }
        __syncthreads();
    }
}

__global__ void k_init(float* out, long long total, int n8){
    long long i = (long long)blockIdx.x*NT + threadIdx.x;
    if (i < total) out[i] = 0.f;
    if (i < n8){ g_mx[i] = 0u; g_sm[i] = 0.f; }
}

__global__ void k_exp(const int* __restrict__ dst, int E){
    int i = blockIdx.x*NT + threadIdx.x;
    if (i >= E*8) return;
    int e = i>>3, h = i&7, d = dst[e];
    float ae = expf(g_a[i] - kdec(g_mx[(size_t)d*8+h]));
    g_aexp[i] = ae;
    atomicAdd(&g_sm[(size_t)d*8+h], ae);
}

__global__ void k_scatter(const int* __restrict__ dst, float* __restrict__ out, int E){
    int t = blockIdx.x*NT + threadIdx.x;
    int e = t >> 7;
    if (e >= E) return;
    int j = (t & 127) * 4, h = j >> 6, d = dst[e];
    float w = g_aexp[e*8+h] / g_sm[(size_t)d*8+h];
    float4 v = *(const float4*)(g_eft + (size_t)e*512 + j);
    float* p = out + (size_t)d*512 + j;
    atomicAdd(p+0, v.x*w); atomicAdd(p+1, v.y*w);
    atomicAdd(p+2, v.z*w); atomicAdd(p+3, v.w*w);
}

extern "C" void kernel_launch(void* const* d_in, const int* in_sizes, int n_in,
                              void* d_out, int out_size)
{
    const float* feat=(const float*)d_in[0];  const float* pos=(const float*)d_in[1];
    const float* siw=(const float*)d_in[2];   const float* sib=(const float*)d_in[3];
    const float* sow=(const float*)d_in[4];   const float* sob=(const float*)d_in[5];
    const float* ciw=(const float*)d_in[6];   const float* cib=(const float*)d_in[7];
    const float* cow=(const float*)d_in[8];   const float* cob=(const float*)d_in[9];
    const float* sl1g=(const float*)d_in[10]; const float* sl1b=(const float*)d_in[11];
    const float* sl2g=(const float*)d_in[12]; const float* sl2b=(const float*)d_in[13];
    const float* cl1g=(const float*)d_in[14]; const float* cl1b=(const float*)d_in[15];
    const float* cl2g=(const float*)d_in[16]; const float* cl2b=(const float*)d_in[17];
    const float* fw1=(const float*)d_in[18];  const float* fb1=(const float*)d_in[19];
    const float* fw2=(const float*)d_in[20];  const float* fb2=(const float*)d_in[21];
    const float* gw1=(const float*)d_in[22];  const float* gb1=(const float*)d_in[23];
    const float* gw2=(const float*)d_in[24];  const float* gb2=(const float*)d_in[25];
    const float* iw=(const float*)d_in[26];   const float* av=(const float*)d_in[27];
    const int* eidx=(const int*)d_in[28];     const int* dst=(const int*)d_in[29];

    int N = in_sizes[0] / 64;
    int E = in_sizes[29];
    float* out = (float*)d_out;
    long long total = (long long)N * 512;

    static int attr_done = 0;
    if (!attr_done){
        cudaFuncSetAttribute(k_mega, cudaFuncAttributeMaxDynamicSharedMemorySize, SMEM_BYTES);
        attr_done = 1;
    }

    k_init<<<(unsigned)((total + NT-1)/NT), NT>>>(out, total, N*8);
    int tiles = (E + TILE - 1) / TILE;
    k_mega<<<tiles, NT, SMEM_BYTES>>>(feat,pos,siw,sib,sow,sob,ciw,cib,cow,cob,
        sl1g,sl1b,sl2g,sl2b,cl1g,cl1b,cl2g,cl2b,
        fw1,fb1,fw2,fb2,gw1,gb1,gw2,gb2,iw,av,eidx,dst,N,E);
    k_exp<<<(E*8 + NT-1)/NT, NT>>>(dst, E);
    k_scatter<<<(E*128 + NT-1)/NT, NT>>>(dst, out, E);
}

// round 15
// speedup vs baseline: 1.3398x; 1.3398x over previous
#include <cuda_runtime.h>
#include <math.h>

#define NT 256
#define TILE 16
#define SEQ 5
#define ROWS (TILE*SEQ)
#define EMAX 150016
#define NMAX 50048

typedef unsigned long long ull;

static __device__ float    g_eft[(size_t)EMAX * 512];
static __device__ float    g_a[EMAX * 8];
static __device__ float    g_aexp[EMAX * 8];
static __device__ unsigned g_mx[NMAX * 8];
static __device__ float    g_sm[NMAX * 8];

// smem layout (floats) — total 27088 fl = 105.8 KB (2 CTAs/SM if regs allow)
#define O_TOK  0
#define O_X    (O_TOK + ROWS*64)
#define O_BUFA (O_X + ROWS*64)
#define O_BUFB (O_BUFA + ROWS*64)
#define O_W    (O_BUFB + ROWS*64)         // 4352 fl: one 64x64 chunk (ldw=68)
#define O_INST (O_W + 4352)
#define O_Q    (O_INST + TILE*64)
#define O_FV   (O_Q + TILE*64)
#define O_DEN  (O_FV + ROWS)
#define O_INT  (O_DEN + TILE)
#define SMEM_FLOATS (O_INT + 112)
#define SMEM_BYTES (SMEM_FLOATS*4)

__device__ __forceinline__ void fma2(ull& c, ull a, ull b){
    asm("fma.rn.f32x2 %0, %1, %2, %0;" : "+l"(c) : "l"(a), "l"(b));
}
__device__ __forceinline__ float hsum2(ull c){
    float lo, hi;
    asm("mov.b64 {%0,%1}, %2;" : "=f"(lo), "=f"(hi) : "l"(c));
    return lo + hi;
}
__device__ __forceinline__ void unpack2(ull c, float& lo, float& hi){
    asm("mov.b64 {%0,%1}, %2;" : "=f"(lo), "=f"(hi) : "l"(c));
}
__device__ __forceinline__ ull bcast2(float s){
    ull r; asm("mov.b64 %0, {%1,%1};" : "=l"(r) : "f"(s)); return r;
}
__device__ __forceinline__ float warpSum(float v){
#pragma unroll
    for (int o=16;o>0;o>>=1) v += __shfl_xor_sync(0xffffffffu, v, o);
    return v;
}
__device__ __forceinline__ float geluf(float x){
    return 0.5f*x*(1.0f+erff(x*0.70710678118654752f));
}
__device__ __forceinline__ unsigned fkey(float f){
    unsigned u = __float_as_uint(f);
    return (u & 0x80000000u) ? ~u : (u | 0x80000000u);
}
__device__ __forceinline__ float kdec(unsigned k){
    return (k & 0x80000000u) ? __uint_as_float(k & 0x7fffffffu) : __uint_as_float(~k);
}

__device__ void stage68(float* dst,const float* src,int srcStride,int tid){
    for (int i = tid; i < 64*16; i += NT){
        int r = i >> 4, c4 = i & 15;
        float4 v = __ldg((const float4*)(src + r*srcStride + c4*4));
        *(float4*)(dst + r*68 + c4*4) = v;
    }
}

// M=80,NC=64,K=64: out[80][ldo] op= X[80][64] @ W^T + bias. 256 exact tasks.
__device__ void gemm80x64(float* out,int ldo,const float* X,
                          const float* Wr,const float* bias,bool acc,int tid){
    int col = tid & 31;
    int r0  = (tid >> 5) * 10;
    const float* W0 = Wr + col*68;
    const float* W1 = Wr + (col+32)*68;
    ull a0[10], a1[10];
#pragma unroll
    for (int i=0;i<10;i++){ a0[i]=0ull; a1[i]=0ull; }
#pragma unroll 4
    for (int k4=0;k4<16;k4++){
        ulonglong2 w0 = *(const ulonglong2*)(W0 + k4*4);
        ulonglong2 w1 = *(const ulonglong2*)(W1 + k4*4);
#pragma unroll
        for (int i=0;i<10;i++){
            ulonglong2 xv = *(const ulonglong2*)(X + (r0+i)*64 + k4*4);
            fma2(a0[i], xv.x, w0.x); fma2(a0[i], xv.y, w0.y);
            fma2(a1[i], xv.x, w1.x); fma2(a1[i], xv.y, w1.y);
        }
    }
    float b0 = __ldg(bias+col), b1 = __ldg(bias+col+32);
#pragma unroll
    for (int i=0;i<10;i++){
        float v0 = hsum2(a0[i]) + b0;
        float v1 = hsum2(a1[i]) + b1;
        float* p0 = out + (r0+i)*ldo + col;
        float* p1 = out + (r0+i)*ldo + col + 32;
        if (acc){ *p0 += v0; *p1 += v1; }
        else    { *p0  = v0; *p1  = v1; }
    }
}

// M=16,NC=64 GEMM, 4-way split-K over K=64, all 256 threads. Contains syncthreads.
__device__ void gemm16x64(float* out,int ldo,const float* X,int ldx,
                          const float* Wr,const float* bias,bool acc,
                          int tid,float* s_part){
    int col = tid & 63, ks = tid >> 6;
    const float* Wc = Wr + col*68 + ks*16;
    const float* Xc = X + ks*16;
    ull a[16];
#pragma unroll
    for (int i=0;i<16;i++) a[i]=0ull;
#pragma unroll
    for (int k4=0;k4<4;k4++){
        ulonglong2 wv = *(const ulonglong2*)(Wc + k4*4);
#pragma unroll
        for (int i=0;i<16;i++){
            ulonglong2 xv = *(const ulonglong2*)(Xc + i*ldx + k4*4);
            fma2(a[i], xv.x, wv.x); fma2(a[i], xv.y, wv.y);
        }
    }
    float* pp = s_part + ks*1024 + col;
#pragma unroll
    for (int i=0;i<16;i++) pp[i*64] = hsum2(a[i]);
    __syncthreads();
    for (int i = tid; i < 1024; i += NT){
        int c2 = i & 63;
        float s = s_part[i] + s_part[1024+i] + s_part[2048+i] + s_part[3072+i];
        float v = s + (bias ? __ldg(bias+c2) : 0.f);
        float* p = out + (i>>6)*ldo + c2;
        if (acc) *p += v; else *p = v;
    }
}

__device__ void ln_rows(const float* in,float* out,int nrows,
                        const float* g,const float* b,int tid){
    int warp = tid >> 5, lane = tid & 31;
    for (int r = warp; r < nrows; r += 8){
        float x0 = in[r*64+lane], x1 = in[r*64+lane+32];
        float s  = warpSum(x0+x1);
        float s2 = warpSum(x0*x0 + x1*x1);
        float m  = s*(1.f/64.f);
        float v  = fmaxf(s2*(1.f/64.f) - m*m, 0.f);
        float rs = rsqrtf(v + 1e-5f);
        out[r*64+lane]    = (x0-m)*rs*__ldg(g+lane)    + __ldg(b+lane);
        out[r*64+lane+32] = (x1-m)*rs*__ldg(g+lane+32) + __ldg(b+lane+32);
    }
}

__global__ void __launch_bounds__(NT)
k_mega(const float* __restrict__ feat,const float* __restrict__ pos,
       const float* __restrict__ siw,const float* __restrict__ sib,
       const float* __restrict__ sow,const float* __restrict__ sob,
       const float* __restrict__ ciw,const float* __restrict__ cib,
       const float* __restrict__ cow,const float* __restrict__ cob,
       const float* __restrict__ sl1g,const float* __restrict__ sl1b,
       const float* __restrict__ sl2g,const float* __restrict__ sl2b,
       const float* __restrict__ cl1g,const float* __restrict__ cl1b,
       const float* __restrict__ cl2g,const float* __restrict__ cl2b,
       const float* __restrict__ fw1,const float* __restrict__ fb1,
       const float* __restrict__ fw2,const float* __restrict__ fb2,
       const float* __restrict__ gw1,const float* __restrict__ gb1,
       const float* __restrict__ gw2,const float* __restrict__ gb2,
       const float* __restrict__ iw,const float* __restrict__ av,
       const int* __restrict__ eidx,const int* __restrict__ dst,int N,int E)
{
    extern __shared__ float sm[];
    float* s_tok = sm + O_TOK;  float* s_x = sm + O_X;
    float* s_bufA= sm + O_BUFA; float* s_bufB= sm + O_BUFB;
    float* s_w   = sm + O_W;
    float* s_inst= sm + O_INST; float* s_q = sm + O_Q;
    float* s_fv  = sm + O_FV;   float* s_den = sm + O_DEN;
    int* s_idx = (int*)(sm + O_INT);
    int* s_dst = s_idx + ROWS;  int* s_lid = s_dst + TILE;
    int tid = threadIdx.x, e0 = blockIdx.x * TILE;
    // per-tile global scratch for attention weights (region overwritten in S7)
    float* g_att = g_eft + (size_t)e0*512;

    // ---- S0 ----
    if (tid < ROWS){
        int e = tid/SEQ, s = tid - e*SEQ, ge = e0 + e;
        int id = (ge < E) ? eidx[ge*SEQ + s] : N;
        s_idx[tid] = id; s_fv[tid] = (id < N) ? 1.f : 0.f;
    }
    __syncthreads();
    if (tid < TILE){
        float c = 0.f;
        for (int s=0;s<SEQ;s++) c += s_fv[tid*SEQ+s];
        s_den[tid] = fmaxf(c, 1.f);
        int lp = (c > 0.f) ? (int)c - 1 : 0;
        s_lid[tid] = s_idx[tid*SEQ + lp];
        int ge = e0 + tid;
        s_dst[tid] = (ge < E) ? dst[ge] : 0;
    }
    for (int i = tid; i < ROWS*64; i += NT){
        int r = i>>6, c = i&63, s = r%SEQ, id = s_idx[r];
        s_tok[i] = (id < N) ? __ldg(feat + (size_t)id*64 + c) + __ldg(pos + s*64 + c) : 0.f;
    }
    __syncthreads();

    // ---- S1: LN1, Q, K ----
    ln_rows(s_tok, s_x, ROWS, sl1g, sl1b, tid);
    stage68(s_w, siw, 64, tid);
    __syncthreads();
    gemm80x64(s_bufA, 64, s_x, s_w, sib, false, tid);       // Q
    __syncthreads();
    stage68(s_w, siw + 64*64, 64, tid);
    __syncthreads();
    gemm80x64(s_bufB, 64, s_x, s_w, sib + 64, false, tid);  // K
    __syncthreads();

    // ---- S2: scores -> g_att scratch; V; apply ----
    {
        stage68(s_w, siw + 128*64, 64, tid);
        if (tid < TILE*8){
            int e = tid>>3, h = tid&7;
            float* ap = g_att + tid*25;
#pragma unroll
            for (int qs=0; qs<SEQ; qs++){
                const ull* qq = (const ull*)(s_bufA + (e*SEQ+qs)*64 + h*8);
                ull q0=qq[0], q1=qq[1], q2=qq[2], q3=qq[3];
                float sc[SEQ], mx = -1e30f;
#pragma unroll
                for (int ks=0; ks<SEQ; ks++){
                    const ull* kk = (const ull*)(s_bufB + (e*SEQ+ks)*64 + h*8);
                    ull acc = 0ull;
                    fma2(acc, q0, kk[0]); fma2(acc, q1, kk[1]);
                    fma2(acc, q2, kk[2]); fma2(acc, q3, kk[3]);
                    float s = hsum2(acc) * 0.35355339059327373f;
                    if (s_fv[e*SEQ+ks] == 0.f) s = -1e9f;
                    sc[ks] = s; mx = fmaxf(mx, s);
                }
                float sum = 0.f;
#pragma unroll
                for (int ks=0; ks<SEQ; ks++){ sc[ks] = expf(sc[ks]-mx); sum += sc[ks]; }
                float inv = 1.f/sum;
#pragma unroll
                for (int ks=0; ks<SEQ; ks++) ap[qs*5+ks] = sc[ks]*inv;
            }
        }
        __syncthreads();
        gemm80x64(s_bufA, 64, s_x, s_w, sib + 128, false, tid);  // V (overwrites Q)
        __syncthreads();
        if (tid < TILE*8){
            int e = tid>>3, h = tid&7;
            const float* ap = g_att + tid*25;
#pragma unroll
            for (int qs=0; qs<SEQ; qs++){
                ull o[4] = {0ull,0ull,0ull,0ull};
#pragma unroll
                for (int ks=0; ks<SEQ; ks++){
                    ull w2 = bcast2(ap[qs*5+ks]);
                    const ull* vv = (const ull*)(s_bufA + (e*SEQ+ks)*64 + h*8);
                    fma2(o[0], w2, vv[0]); fma2(o[1], w2, vv[1]);
                    fma2(o[2], w2, vv[2]); fma2(o[3], w2, vv[3]);
                }
                float* op = s_x + (e*SEQ+qs)*64 + h*8;
#pragma unroll
                for (int j=0;j<4;j++){
                    float lo, hi; unpack2(o[j], lo, hi);
                    op[2*j] = lo; op[2*j+1] = hi;
                }
            }
        }
        stage68(s_w, sow, 64, tid);
        __syncthreads();
        gemm80x64(s_tok, 64, s_x, s_w, sob, true, tid);
        __syncthreads();
    }

    // ---- S3: masked mean pool ----
    for (int i = tid; i < TILE*64; i += NT){
        int e = i>>6, c = i&63; float s = 0.f;
#pragma unroll
        for (int ss=0; ss<SEQ; ss++) s += s_fv[e*SEQ+ss]*s_tok[(e*SEQ+ss)*64+c];
        s_inst[i] = s / s_den[e];
    }
    __syncthreads();

    // ---- S4: FF (sa) ----
    ln_rows(s_inst, s_x, TILE, sl2g, sl2b, tid);
    for (int c = 0; c < 4; c++){
        stage68(s_w, fw1 + c*64*64, 64, tid);
        __syncthreads();
        gemm16x64(s_bufA + c*64, 256, s_x, 64, s_w, fb1 + c*64, false, tid, s_x+1024);
        __syncthreads();
    }
    for (int i = tid; i < TILE*256; i += NT) s_bufA[i] = geluf(s_bufA[i]);
    __syncthreads();
    for (int c = 0; c < 4; c++){
        stage68(s_w, fw2 + c*64, 256, tid);
        __syncthreads();
        gemm16x64(s_inst, 64, s_bufA + c*64, 256, s_w, c==0?fb2:(const float*)0, true, tid, s_x+1024);
        __syncthreads();
    }

    // ---- S5: cross attention ----
    for (int i = tid; i < TILE*64; i += NT){
        int e = i>>6, c = i&63, id = s_lid[e];
        s_x[i] = (id < N) ? __ldg(feat + (size_t)id*64 + c) : 0.f;
    }
    __syncthreads();
    ln_rows(s_x, s_x, TILE, cl1g, cl1b, tid);
    stage68(s_w, ciw, 64, tid);
    __syncthreads();
    gemm16x64(s_q, 64, s_x, 64, s_w, cib, false, tid, s_x+1024);
    __syncthreads();
    stage68(s_w, ciw + 64*64, 64, tid);
    __syncthreads();
    gemm80x64(s_bufB, 64, s_tok, s_w, cib + 64, false, tid);       // K
    __syncthreads();
    {
        stage68(s_w, ciw + 128*64, 64, tid);
        if (tid < TILE*8){
            int e = tid>>3, h = tid&7;
            const ull* qq = (const ull*)(s_q + e*64 + h*8);
            ull q0=qq[0], q1=qq[1], q2=qq[2], q3=qq[3];
            float csc[SEQ], mx = -1e30f;
#pragma unroll
            for (int ks=0; ks<SEQ; ks++){
                const ull* kk = (const ull*)(s_bufB + (e*SEQ+ks)*64 + h*8);
                ull acc = 0ull;
                fma2(acc, q0, kk[0]); fma2(acc, q1, kk[1]);
                fma2(acc, q2, kk[2]); fma2(acc, q3, kk[3]);
                float s = hsum2(acc) * 0.35355339059327373f;
                if (s_fv[e*SEQ+ks] == 0.f) s = -1e9f;
                csc[ks] = s; mx = fmaxf(mx, s);
            }
            float sum = 0.f;
#pragma unroll
            for (int ks=0; ks<SEQ; ks++){ csc[ks] = expf(csc[ks]-mx); sum += csc[ks]; }
            float inv = 1.f/sum;
            float* ap = g_att + 3200 + tid*5;
#pragma unroll
            for (int ks=0; ks<SEQ; ks++) ap[ks] = csc[ks]*inv;
        }
        __syncthreads();
        gemm80x64(s_bufA, 64, s_tok, s_w, cib + 128, false, tid);  // V
        __syncthreads();
        if (tid < TILE*8){
            int e = tid>>3, h = tid&7;
            const float* ap = g_att + 3200 + tid*5;
            ull o[4] = {0ull,0ull,0ull,0ull};
#pragma unroll
            for (int ks=0; ks<SEQ; ks++){
                ull w2 = bcast2(ap[ks]);
                const ull* vv = (const ull*)(s_bufA + (e*SEQ+ks)*64 + h*8);
                fma2(o[0], w2, vv[0]); fma2(o[1], w2, vv[1]);
                fma2(o[2], w2, vv[2]); fma2(o[3], w2, vv[3]);
            }
            float* op = s_x + e*64 + h*8;
#pragma unroll
            for (int j=0;j<4;j++){
                float lo, hi; unpack2(o[j], lo, hi);
                op[2*j] = lo; op[2*j+1] = hi;
            }
        }
        stage68(s_w, cow, 64, tid);
        __syncthreads();
        gemm16x64(s_inst, 64, s_x, 64, s_w, cob, true, tid, s_x+1024);
        __syncthreads();
    }

    // ---- S6: FF (ca) ----
    ln_rows(s_inst, s_x, TILE, cl2g, cl2b, tid);
    for (int c = 0; c < 4; c++){
        stage68(s_w, gw1 + c*64*64, 64, tid);
        __syncthreads();
        gemm16x64(s_bufA + c*64, 256, s_x, 64, s_w, gb1 + c*64, false, tid, s_x+1024);
        __syncthreads();
    }
    for (int i = tid; i < TILE*256; i += NT) s_bufA[i] = geluf(s_bufA[i]);
    __syncthreads();
    for (int c = 0; c < 4; c++){
        stage68(s_w, gw2 + c*64, 256, tid);
        __syncthreads();
        gemm16x64(s_inst, 64, s_bufA + c*64, 256, s_w, c==0?gb2:(const float*)0, true, tid, s_x+1024);
        __syncthreads();
    }

    // ---- S7: eft per head + leaky score + seg max ----
    for (int h = 0; h < 8; h++){
        stage68(s_w, iw + h*64*64, 64, tid);
        __syncthreads();
        gemm16x64(s_bufA, 64, s_inst, 64, s_w, (const float*)0, false, tid, s_x+1024);
        __syncthreads();
        {
            int i = tid*4;
            int r = i>>6, c = i&63, ge = e0 + r;
            if (ge < E)
                *(float4*)(g_eft + (size_t)ge*512 + h*64 + c) = *(const float4*)(s_bufA + i);
        }
        if (tid < TILE){
            int e = tid, ge = e0 + e;
            float v = 0.f;
            for (int d=0; d<64; d++) v += s_bufA[e*64 + d]*__ldg(av + h*64 + d);
            v = (v > 0.f) ? v : 0.01f*v;
            if (ge < E){
                g_a[ge*8+h] = v;
                atomicMax(&g_mx[(size_t)s_dst[e]*8 + h], fkey(v));
            }
        }
        __syncthreads();
    }
}

__global__ void k_init(float* out, long long total, int n8){
    long long i = (long long)blockIdx.x*NT + threadIdx.x;
    if (i < total) out[i] = 0.f;
    if (i < n8){ g_mx[i] = 0u; g_sm[i] = 0.f; }
}

__global__ void k_exp(const int* __restrict__ dst, int E){
    int i = blockIdx.x*NT + threadIdx.x;
    if (i >= E*8) return;
    int e = i>>3, h = i&7, d = dst[e];
    float ae = expf(g_a[i] - kdec(g_mx[(size_t)d*8+h]));
    g_aexp[i] = ae;
    atomicAdd(&g_sm[(size_t)d*8+h], ae);
}

__global__ void k_scatter(const int* __restrict__ dst, float* __restrict__ out, int E){
    int t = blockIdx.x*NT + threadIdx.x;
    int e = t >> 7;
    if (e >= E) return;
    int j = (t & 127) * 4, h = j >> 6, d = dst[e];
    float w = g_aexp[e*8+h] / g_sm[(size_t)d*8+h];
    float4 v = *(const float4*)(g_eft + (size_t)e*512 + j);
    float* p = out + (size_t)d*512 + j;
    atomicAdd(p+0, v.x*w); atomicAdd(p+1, v.y*w);
    atomicAdd(p+2, v.z*w); atomicAdd(p+3, v.w*w);
}

extern "C" void kernel_launch(void* const* d_in, const int* in_sizes, int n_in,
                              void* d_out, int out_size)
{
    const float* feat=(const float*)d_in[0];  const float* pos=(const float*)d_in[1];
    const float* siw=(const float*)d_in[2];   const float* sib=(const float*)d_in[3];
    const float* sow=(const float*)d_in[4];   const float* sob=(const float*)d_in[5];
    const float* ciw=(const float*)d_in[6];   const float* cib=(const float*)d_in[7];
    const float* cow=(const float*)d_in[8];   const float* cob=(const float*)d_in[9];
    const float* sl1g=(const float*)d_in[10]; const float* sl1b=(const float*)d_in[11];
    const float* sl2g=(const float*)d_in[12]; const float* sl2b=(const float*)d_in[13];
    const float* cl1g=(const float*)d_in[14]; const float* cl1b=(const float*)d_in[15];
    const float* cl2g=(const float*)d_in[16]; const float* cl2b=(const float*)d_in[17];
    const float* fw1=(const float*)d_in[18];  const float* fb1=(const float*)d_in[19];
    const float* fw2=(const float*)d_in[20];  const float* fb2=(const float*)d_in[21];
    const float* gw1=(const float*)d_in[22];  const float* gb1=(const float*)d_in[23];
    const float* gw2=(const float*)d_in[24];  const float* gb2=(const float*)d_in[25];
    const float* iw=(const float*)d_in[26];   const float* av=(const float*)d_in[27];
    const int* eidx=(const int*)d_in[28];     const int* dst=(const int*)d_in[29];

    int N = in_sizes[0] / 64;
    int E = in_sizes[29];
    float* out = (float*)d_out;
    long long total = (long long)N * 512;

    cudaFuncSetAttribute(k_mega, cudaFuncAttributeMaxDynamicSharedMemorySize, SMEM_BYTES);

    k_init<<<(unsigned)((total + NT-1)/NT), NT>>>(out, total, N*8);
    int tiles = (E + TILE - 1) / TILE;
    k_mega<<<tiles, NT, SMEM_BYTES>>>(feat,pos,siw,sib,sow,sob,ciw,cib,cow,cob,
        sl1g,sl1b,sl2g,sl2b,cl1g,cl1b,cl2g,cl2b,
        fw1,fb1,fw2,fb2,gw1,gb1,gw2,gb2,iw,av,eidx,dst,N,E);
    k_exp<<<(E*8 + NT-1)/NT, NT>>>(dst, E);
    k_scatter<<<(E*128 + NT-1)/NT, NT>>>(dst, out, E);
}